// round 8
// baseline (speedup 1.0000x reference)
#include <cuda_runtime.h>
#include <math.h>

#define BB 32
#define NN 4096
#define KVN 1024
#define DD 1024
#define HH 16
#define LL 2
#define MAXFV 4096
#define MS 32   // mean slices

// ---------- scratch ----------
__device__ __align__(16) float g_q[64 * DD];
__device__ __align__(16) float g_x[64 * DD];
__device__ __align__(16) float g_qkv[64 * 3 * DD];
__device__ __align__(16) float g_attn[64 * DD];
__device__ __align__(16) float g_qp[BB * DD];
__device__ __align__(16) float g_u[BB * HH * DD];
__device__ __align__(16) float g_c[BB * HH * DD];
__device__ __align__(16) float g_part[16 * 64 * 4096];
__device__ __align__(16) float g_cpart[16 * BB * HH * DD];   // attn slice partials
__device__ __align__(16) float g_ms[16 * BB * HH * 2];       // per-slice (max, sumexp)
__device__ __align__(16) float g_mpart[MS * BB * DD];
__device__ __align__(16) float g_h[64 * 4096];

// ---------- packed f32x2 helpers ----------
__device__ __forceinline__ unsigned long long pack2(float lo, float hi) {
    unsigned long long r;
    asm("mov.b64 %0, {%1, %2};" : "=l"(r) : "f"(lo), "f"(hi));
    return r;
}
__device__ __forceinline__ float2 unpack2(unsigned long long v) {
    float2 r;
    asm("mov.b64 {%0, %1}, %2;" : "=f"(r.x), "=f"(r.y) : "l"(v));
    return r;
}
__device__ __forceinline__ void ffma2(unsigned long long& d, unsigned long long a,
                                      unsigned long long b) {
    asm("fma.rn.f32x2 %0, %1, %2, %0;" : "+l"(d) : "l"(a), "l"(b));
}
__device__ __forceinline__ void mul2(unsigned long long& d, unsigned long long a) {
    asm("mul.rn.f32x2 %0, %0, %1;" : "+l"(d) : "l"(a));
}

// ---------- block reductions ----------
__device__ __forceinline__ float blkredSum(float v) {
    __shared__ float sm[8];
    __shared__ float outv;
    int tid = threadIdx.x;
#pragma unroll
    for (int o = 16; o; o >>= 1) v += __shfl_xor_sync(0xffffffffu, v, o);
    if ((tid & 31) == 0) sm[tid >> 5] = v;
    __syncthreads();
    if (tid == 0) {
        float a = 0.f;
        int nw = blockDim.x >> 5;
        for (int w = 0; w < nw; w++) a += sm[w];
        outv = a;
    }
    __syncthreads();
    float r = outv;
    __syncthreads();
    return r;
}

// ---------- partial mean of frame_tokens: grid (2, BB, MS), block 128 ----------
__global__ void meanpart_k(const float* __restrict__ X) {
    int b = blockIdx.y, s = blockIdx.z;
    int c0 = blockIdx.x * 512 + threadIdx.x * 4;
    const int RS = NN / MS;
    const float* base = X + ((size_t)b * NN + (size_t)s * RS) * DD + c0;
    float4 acc = make_float4(0.f, 0.f, 0.f, 0.f);
    for (int j = 0; j < RS; j += 4) {
        float4 v0 = *(const float4*)(base + (size_t)(j + 0) * DD);
        float4 v1 = *(const float4*)(base + (size_t)(j + 1) * DD);
        float4 v2 = *(const float4*)(base + (size_t)(j + 2) * DD);
        float4 v3 = *(const float4*)(base + (size_t)(j + 3) * DD);
        acc.x += (v0.x + v1.x) + (v2.x + v3.x);
        acc.y += (v0.y + v1.y) + (v2.y + v3.y);
        acc.z += (v0.z + v1.z) + (v2.z + v3.z);
        acc.w += (v0.w + v1.w) + (v2.w + v3.w);
    }
    *(float4*)(g_mpart + (size_t)(s * BB + b) * DD + c0) = acc;
}

// ---------- q init: grid 256, block 256 ----------
__global__ void initq_k(const float* __restrict__ max_init,
                        const float* __restrict__ qbase,
                        const float* __restrict__ rolew,
                        const float* __restrict__ timew,
                        const int* __restrict__ fidx) {
    int idx = blockIdx.x * 256 + threadIdx.x;
    int b = idx >> 11, r = idx & 2047, t = r >> 10, d = r & 1023;
    float base;
    if (t == 0) {
        float m = 0.f;
#pragma unroll
        for (int s = 0; s < MS; s++) m += g_mpart[(size_t)(s * BB + b) * DD + d];
        base = m * (1.0f / NN);
    } else {
        base = max_init[b * DD + d];
    }
    int fi = fidx[b];
    fi = fi < 0 ? 0 : (fi > MAXFV - 1 ? MAXFV - 1 : fi);
    g_q[idx] = base + qbase[t * DD + d] + rolew[t * DD + d] + timew[(size_t)fi * DD + d];
}

// ---------- LayerNorm rows: grid rows, block 256 ----------
__global__ void ln_k(const float* __restrict__ in, const float* __restrict__ gg,
                     const float* __restrict__ bb, float* __restrict__ out) {
    int row = blockIdx.x, tid = threadIdx.x;
    float4 xv = ((const float4*)(in + (size_t)row * DD))[tid];
    float s = blkredSum(xv.x + xv.y + xv.z + xv.w);
    float mean = s * (1.0f / DD);
    float d0 = xv.x - mean, d1 = xv.y - mean, d2 = xv.z - mean, d3 = xv.w - mean;
    float ss = blkredSum(d0 * d0 + d1 * d1 + d2 * d2 + d3 * d3);
    float inv = rsqrtf(ss * (1.0f / DD) + 1e-5f);
    float4 g4 = ((const float4*)gg)[tid];
    float4 b4 = ((const float4*)bb)[tid];
    float4 o;
    o.x = d0 * inv * g4.x + b4.x;
    o.y = d1 * inv * g4.y + b4.y;
    o.z = d2 * inv * g4.z + b4.z;
    o.w = d3 * inv * g4.w + b4.w;
    ((float4*)(out + (size_t)row * DD))[tid] = o;
}

// ---------- split-K GEMM, transposed smem + FFMA2 ----------
__global__ void gemm_k(const float* __restrict__ A, int lda, long long sA,
                       const float* __restrict__ W, int ldw, long long sW,
                       float* __restrict__ part, int Ntot, int M, int Ktot, int SK) {
    int z = blockIdx.z;
    int bt = z / SK, s = z - bt * SK;
    A += (long long)bt * sA;
    W += (long long)bt * sW;
    float* P = part + ((long long)(bt * SK + s) * M) * Ntot;
    int Ks = Ktot / SK, kbase = s * Ks;
    int n0 = blockIdx.x * 64;
    __shared__ __align__(16) float As[16][68];
    __shared__ __align__(16) float Ws[16][68];
    int tid = threadIdx.x;
    int tx = tid & 15, ty = tid >> 4;
    int lr = tid >> 2, lc = (tid & 3) * 4;
    unsigned long long acc01[4], acc23[4];
#pragma unroll
    for (int j = 0; j < 4; j++) { acc01[j] = 0ull; acc23[j] = 0ull; }
    for (int kc = kbase; kc < kbase + Ks; kc += 16) {
        float4 av = make_float4(0.f, 0.f, 0.f, 0.f);
        if (lr < M) av = *(const float4*)(A + (long long)lr * lda + kc + lc);
        As[lc + 0][lr] = av.x; As[lc + 1][lr] = av.y;
        As[lc + 2][lr] = av.z; As[lc + 3][lr] = av.w;
        float4 wv = *(const float4*)(W + (long long)(n0 + lr) * ldw + kc + lc);
        Ws[lc + 0][lr] = wv.x; Ws[lc + 1][lr] = wv.y;
        Ws[lc + 2][lr] = wv.z; Ws[lc + 3][lr] = wv.w;
        __syncthreads();
#pragma unroll
        for (int kk = 0; kk < 16; kk++) {
            float4 a4 = *(const float4*)&As[kk][ty * 4];
            float4 w4 = *(const float4*)&Ws[kk][tx * 4];
            unsigned long long a01 = pack2(a4.x, a4.y);
            unsigned long long a23 = pack2(a4.z, a4.w);
            unsigned long long w0 = pack2(w4.x, w4.x);
            unsigned long long w1 = pack2(w4.y, w4.y);
            unsigned long long w2 = pack2(w4.z, w4.z);
            unsigned long long w3 = pack2(w4.w, w4.w);
            ffma2(acc01[0], a01, w0); ffma2(acc23[0], a23, w0);
            ffma2(acc01[1], a01, w1); ffma2(acc23[1], a23, w1);
            ffma2(acc01[2], a01, w2); ffma2(acc23[2], a23, w2);
            ffma2(acc01[3], a01, w3); ffma2(acc23[3], a23, w3);
        }
        __syncthreads();
    }
    float2 r0 = unpack2(acc01[0]), r1 = unpack2(acc01[1]);
    float2 r2 = unpack2(acc01[2]), r3 = unpack2(acc01[3]);
    float2 s0 = unpack2(acc23[0]), s1 = unpack2(acc23[1]);
    float2 s2 = unpack2(acc23[2]), s3 = unpack2(acc23[3]);
    int m0 = ty * 4, nn = n0 + tx * 4;
    if (m0 + 0 < M) *(float4*)&P[(long long)(m0 + 0) * Ntot + nn] = make_float4(r0.x, r1.x, r2.x, r3.x);
    if (m0 + 1 < M) *(float4*)&P[(long long)(m0 + 1) * Ntot + nn] = make_float4(r0.y, r1.y, r2.y, r3.y);
    if (m0 + 2 < M) *(float4*)&P[(long long)(m0 + 2) * Ntot + nn] = make_float4(s0.x, s1.x, s2.x, s3.x);
    if (m0 + 3 < M) *(float4*)&P[(long long)(m0 + 3) * Ntot + nn] = make_float4(s0.y, s1.y, s2.y, s3.y);
}

// ---------- combine split-K + bias; mode 0 store, 1 gelu-store, 2 residual-add ----------
__global__ void combine_k(const float* __restrict__ part, int S, int M, int N,
                          const float* __restrict__ bias, int biasBatch,
                          float* __restrict__ dst, int dstRow, int dstBatch,
                          int mode, int total) {
    int idx = blockIdx.x * 256 + threadIdx.x;
    if (idx >= total) return;
    int bt = idx / (M * N);
    int r = idx - bt * M * N;
    int m = r / N, n = r - m * N;
    float v = 0.f;
    const float* p = part + ((long long)bt * S * M + m) * N + n;
    for (int s = 0; s < S; s++) v += p[(long long)s * M * N];
    if (bias) v += bias[bt * biasBatch + n];
    if (mode == 1) v = 0.5f * v * (1.0f + erff(v * 0.70710678118654752f));
    float* dp = dst + (long long)bt * dstBatch + (long long)m * dstRow + n;
    if (mode == 2) *dp += v; else *dp = v;
}

// ---------- self-attn over 2 tokens: grid (BB, HH), block 64 ----------
__global__ void sattn_k() {
    int b = blockIdx.x, h = blockIdx.y, i = threadIdx.x;
    int r0 = (b * 2) * 3 * DD, r1 = r0 + 3 * DD;
    int cq = h * 64 + i, ck = DD + cq, cv = 2 * DD + cq;
    float q0 = g_qkv[r0 + cq], q1 = g_qkv[r1 + cq];
    float k0 = g_qkv[r0 + ck], k1 = g_qkv[r1 + ck];
    float v0 = g_qkv[r0 + cv], v1 = g_qkv[r1 + cv];
    __shared__ float red[4][64];
    red[0][i] = q0 * k0; red[1][i] = q0 * k1;
    red[2][i] = q1 * k0; red[3][i] = q1 * k1;
    __syncthreads();
    __shared__ float ss[4];
    if (i < 4) {
        float a = 0.f;
        for (int j = 0; j < 64; j++) a += red[i][j];
        ss[i] = a * 0.125f;
    }
    __syncthreads();
    float m0 = fmaxf(ss[0], ss[1]);
    float e00 = __expf(ss[0] - m0), e01 = __expf(ss[1] - m0);
    float o0 = (e00 * v0 + e01 * v1) / (e00 + e01);
    float m1 = fmaxf(ss[2], ss[3]);
    float e10 = __expf(ss[2] - m1), e11 = __expf(ss[3] - m1);
    float o1 = (e10 * v0 + e11 * v1) / (e10 + e11);
    g_attn[(size_t)(b * 2) * DD + h * 64 + i] = o0;
    g_attn[(size_t)(b * 2 + 1) * DD + h * 64 + i] = o1;
}

// ---------- u = 0.125 * Wk_h^T (qp_h + bq_h): grid (HH, DD/64), block 256 ----------
__global__ void u_k(const float* __restrict__ Wk, const float* __restrict__ bq) {
    int h = blockIdx.x;
    int d0 = blockIdx.y * 64;
    int tid = threadIdx.x;
    __shared__ float qps[32 * 64];
    for (int t = tid; t < 2048; t += 256) {
        int b = t >> 6, i = t & 63;
        qps[t] = g_qp[b * DD + h * 64 + i] + bq[h * 64 + i];
    }
    __syncthreads();
    int d = d0 + (tid & 63);
    int bg = tid >> 6;
    float acc[8];
#pragma unroll
    for (int r = 0; r < 8; r++) acc[r] = 0.f;
    const float* wp = Wk + (size_t)(h * 64) * DD + d;
    for (int i = 0; i < 64; i++) {
        float w = wp[(size_t)i * DD];
#pragma unroll
        for (int r = 0; r < 8; r++) acc[r] += qps[(bg * 8 + r) * 64 + i] * w;
    }
#pragma unroll
    for (int r = 0; r < 8; r++)
        g_u[((size_t)(bg * 8 + r) * HH + h) * DD + d] = acc[r] * 0.125f;
}

// ---------- fused flash cross-attention ----------
// grid (SL, BB), block 256. One CTA: j-slice of Nkv rows, all 16 heads, all 1024 d.
// Writes per-slice partials: g_cpart[(s*BB+b)*HH+h][d] (unnormalized, local max ref)
// and g_ms[((s*BB+b)*HH+h)*2] = {running max, running sumexp}.
__global__ void fattn_k(const float* __restrict__ X, int Nkv, int SL) {
    int s = blockIdx.x, b = blockIdx.y;
    int rows = Nkv / SL;
    int j0 = s * rows;
    int tid = threadIdx.x;
    __shared__ __align__(16) float Xs[32][68];                 // [kk][j]
    __shared__ __align__(16) float Us[32][20];                 // [kk][h]
    __shared__ __align__(16) float Sc[16][66];                 // raw scores [h][j]
    __shared__ __align__(16) unsigned long long Ps[16][64];    // {p,p}
    __shared__ float Ms[16], Ss[16], Fs[16];
    int ja = tid >> 2;            // phase A: row in tile (0..63)
    int hg = (tid & 3) * 4;       // phase A: head group base
    int d0 = tid * 4;             // phase B: d columns
    unsigned long long acc01[16], acc23[16];
#pragma unroll
    for (int h = 0; h < 16; h++) { acc01[h] = 0ull; acc23[h] = 0ull; }
    if (tid < 16) { Ms[tid] = -1e30f; Ss[tid] = 0.f; }
    const float* Ub = g_u + (size_t)b * HH * DD;
    for (int jt = 0; jt < rows; jt += 64) {
        const float* Xt = X + ((size_t)b * Nkv + j0 + jt) * DD;
        // -------- phase A: scores for 64 rows --------
        unsigned long long sc01 = 0ull, sc23 = 0ull;
        for (int k0 = 0; k0 < DD; k0 += 32) {
#pragma unroll
            for (int q = 0; q < 2; q++) {
                int t = tid + q * 256;
                int row = t >> 3;
                int c4 = (t & 7) * 4;
                float4 xv = *(const float4*)(Xt + (size_t)row * DD + k0 + c4);
                Xs[c4 + 0][row] = xv.x; Xs[c4 + 1][row] = xv.y;
                Xs[c4 + 2][row] = xv.z; Xs[c4 + 3][row] = xv.w;
            }
            if (tid < 128) {
                int h = tid >> 3, c4 = (tid & 7) * 4;
                float4 uv = *(const float4*)(Ub + (size_t)h * DD + k0 + c4);
                Us[c4 + 0][h] = uv.x; Us[c4 + 1][h] = uv.y;
                Us[c4 + 2][h] = uv.z; Us[c4 + 3][h] = uv.w;
            }
            __syncthreads();
#pragma unroll
            for (int kk = 0; kk < 32; kk++) {
                float xv = Xs[kk][ja];
                float4 u4 = *(const float4*)&Us[kk][hg];
                unsigned long long xx = pack2(xv, xv);
                ffma2(sc01, xx, pack2(u4.x, u4.y));
                ffma2(sc23, xx, pack2(u4.z, u4.w));
            }
            __syncthreads();
        }
        {
            float2 a = unpack2(sc01), c = unpack2(sc23);
            Sc[hg + 0][ja] = a.x; Sc[hg + 1][ja] = a.y;
            Sc[hg + 2][ja] = c.x; Sc[hg + 3][ja] = c.y;
        }
        __syncthreads();
        // -------- online softmax update (8 warps x 2 heads) --------
        {
            int w = tid >> 5, lane = tid & 31;
#pragma unroll
            for (int hh = 0; hh < 2; hh++) {
                int h = w * 2 + hh;
                float v0 = Sc[h][lane], v1 = Sc[h][lane + 32];
                float tm = fmaxf(v0, v1);
#pragma unroll
                for (int o = 16; o; o >>= 1) tm = fmaxf(tm, __shfl_xor_sync(0xffffffffu, tm, o));
                float mold = Ms[h];
                float mnew = fmaxf(mold, tm);
                float p0 = __expf(v0 - mnew), p1 = __expf(v1 - mnew);
                Ps[h][lane] = pack2(p0, p0);
                Ps[h][lane + 32] = pack2(p1, p1);
                float ts = p0 + p1;
#pragma unroll
                for (int o = 16; o; o >>= 1) ts += __shfl_xor_sync(0xffffffffu, ts, o);
                if (lane == 0) {
                    float f = __expf(mold - mnew);
                    Fs[h] = f;
                    Ss[h] = Ss[h] * f + ts;
                    Ms[h] = mnew;
                }
            }
        }
        __syncthreads();
        // -------- rescale accumulators --------
#pragma unroll
        for (int h = 0; h < 16; h++) {
            float f = Fs[h];
            unsigned long long ff = pack2(f, f);
            mul2(acc01[h], ff);
            mul2(acc23[h], ff);
        }
        // -------- phase B: accumulate p * x (tile re-read, L2-resident) --------
        const float* Xb = Xt + d0;
#pragma unroll 4
        for (int jj = 0; jj < 64; jj++) {
            float4 x4 = *(const float4*)(Xb + (size_t)jj * DD);
            unsigned long long x01 = pack2(x4.x, x4.y);
            unsigned long long x23 = pack2(x4.z, x4.w);
#pragma unroll
            for (int h = 0; h < 16; h++) {
                unsigned long long pd = Ps[h][jj];
                ffma2(acc01[h], x01, pd);
                ffma2(acc23[h], x23, pd);
            }
        }
        __syncthreads();
    }
    // -------- write slice partials --------
    float* cp = g_cpart + ((size_t)(s * BB + b) * HH) * DD + d0;
#pragma unroll
    for (int h = 0; h < 16; h++) {
        float2 a = unpack2(acc01[h]);
        float2 c = unpack2(acc23[h]);
        *(float4*)(cp + (size_t)h * DD) = make_float4(a.x, a.y, c.x, c.y);
    }
    if (tid < 16) {
        size_t idx = ((size_t)(s * BB + b) * HH + tid) * 2;
        g_ms[idx + 0] = Ms[tid];
        g_ms[idx + 1] = Ss[tid];
    }
}

// ---------- merge slice partials: grid BB*HH, block 256 ----------
__global__ void merge_k(int SL) {
    int bh = blockIdx.x, tid = threadIdx.x;
    __shared__ float wgt[16];
    __shared__ float invS;
    if (tid == 0) {
        float M = -1e30f;
        for (int sl = 0; sl < SL; sl++)
            M = fmaxf(M, g_ms[((size_t)sl * BB * HH + bh) * 2]);
        float S = 0.f;
        for (int sl = 0; sl < SL; sl++) {
            float e = __expf(g_ms[((size_t)sl * BB * HH + bh) * 2] - M);
            wgt[sl] = e;
            S += g_ms[((size_t)sl * BB * HH + bh) * 2 + 1] * e;
        }
        invS = 1.0f / S;
    }
    __syncthreads();
    int d0 = tid * 4;
    float4 acc = make_float4(0.f, 0.f, 0.f, 0.f);
    for (int sl = 0; sl < SL; sl++) {
        float w = wgt[sl];
        float4 v = *(const float4*)(g_cpart + ((size_t)sl * BB * HH + bh) * DD + d0);
        acc.x += w * v.x; acc.y += w * v.y;
        acc.z += w * v.z; acc.w += w * v.w;
    }
    float is = invS;
    *(float4*)(g_c + (size_t)bh * DD + d0) =
        make_float4(acc.x * is, acc.y * is, acc.z * is, acc.w * is);
}

// ---------- host side ----------
struct Scratch {
    float *q, *x, *qkv, *attn, *qp, *c, *part, *h;
};

static void cross_attn(const Scratch& S, const float* X, int Nkv, int SL,
                       const float* inW, const float* inB,
                       const float* outW, const float* outB, int tok) {
    // qp = qn[:,tok] @ wq^T
    gemm_k<<<dim3(16, 1, 8), 256>>>(S.x + tok * DD, 2 * DD, 0, inW, DD, 0, S.part, DD, BB, DD, 8);
    combine_k<<<128, 256>>>(S.part, 8, BB, DD, nullptr, 0, S.qp, DD, 0, 0, BB * DD);
    u_k<<<dim3(HH, DD / 64), 256>>>(inW + (size_t)DD * DD, inB);
    fattn_k<<<dim3(SL, BB), 256>>>(X, Nkv, SL);
    merge_k<<<BB * HH, 256>>>(SL);
    // o[b, h*64+n] = Wv_h c[b,h,:] + bv
    gemm_k<<<dim3(1, 1, HH * 8), 256>>>(S.c, HH * DD, DD, inW + (size_t)2 * DD * DD, DD,
                                        (long long)64 * DD, S.part, 64, BB, DD, 8);
    combine_k<<<128, 256>>>(S.part, 8, BB, 64, inB + 2 * DD, 64, S.qp, DD, 64, 0, HH * BB * 64);
    // q[:,tok] += o @ out_w^T + out_b
    gemm_k<<<dim3(16, 1, 8), 256>>>(S.qp, DD, 0, outW, DD, 0, S.part, DD, BB, DD, 8);
    combine_k<<<128, 256>>>(S.part, 8, BB, DD, outB, 0, S.q + tok * DD, 2 * DD, 0, 2, BB * DD);
}

extern "C" void kernel_launch(void* const* d_in, const int* in_sizes, int n_in,
                              void* d_out, int out_size) {
    const float* FT   = (const float*)d_in[0];
    const float* KV   = (const float*)d_in[1];
    const float* MAXI = (const float*)d_in[2];
    const float* QB   = (const float*)d_in[3];
    const float* RW   = (const float*)d_in[4];
    const float* TW   = (const float*)d_in[5];
    const float* LN1G = (const float*)d_in[6];
    const float* LN1B = (const float*)d_in[7];
    const float* SAIW = (const float*)d_in[8];
    const float* SAIB = (const float*)d_in[9];
    const float* SAOW = (const float*)d_in[10];
    const float* SAOB = (const float*)d_in[11];
    const float* LN2G = (const float*)d_in[12];
    const float* LN2B = (const float*)d_in[13];
    const float* CGIW = (const float*)d_in[14];
    const float* CGIB = (const float*)d_in[15];
    const float* CGOW = (const float*)d_in[16];
    const float* CGOB = (const float*)d_in[17];
    const float* CSIW = (const float*)d_in[18];
    const float* CSIB = (const float*)d_in[19];
    const float* CSOW = (const float*)d_in[20];
    const float* CSOB = (const float*)d_in[21];
    const float* LN3G = (const float*)d_in[22];
    const float* LN3B = (const float*)d_in[23];
    const float* F1W  = (const float*)d_in[24];
    const float* F1B  = (const float*)d_in[25];
    const float* F2W  = (const float*)d_in[26];
    const float* F2B  = (const float*)d_in[27];
    const float* OUTG = (const float*)d_in[28];
    const float* OUTB = (const float*)d_in[29];
    const int*   FIDX = (const int*)d_in[30];

    Scratch S;
    cudaGetSymbolAddress((void**)&S.q,    g_q);
    cudaGetSymbolAddress((void**)&S.x,    g_x);
    cudaGetSymbolAddress((void**)&S.qkv,  g_qkv);
    cudaGetSymbolAddress((void**)&S.attn, g_attn);
    cudaGetSymbolAddress((void**)&S.qp,   g_qp);
    cudaGetSymbolAddress((void**)&S.c,    g_c);
    cudaGetSymbolAddress((void**)&S.part, g_part);
    cudaGetSymbolAddress((void**)&S.h,    g_h);

    meanpart_k<<<dim3(2, BB, MS), 128>>>(FT);
    initq_k<<<256, 256>>>(MAXI, QB, RW, TW, FIDX);

    for (int l = 0; l < LL; l++) {
        size_t o1 = (size_t)l * DD, o3 = (size_t)l * 3 * DD;
        size_t oDD = (size_t)l * DD * DD, o3DD = (size_t)l * 3 * DD * DD;
        size_t o4DD = (size_t)l * 4 * DD * DD, o4D = (size_t)l * 4 * DD;
        // self-attn
        ln_k<<<64, 256>>>(S.q, LN1G + o1, LN1B + o1, S.x);
        gemm_k<<<dim3(48, 1, 8), 256>>>(S.x, DD, 0, SAIW + o3DD, DD, 0, S.part, 3 * DD, 64, DD, 8);
        combine_k<<<768, 256>>>(S.part, 8, 64, 3 * DD, SAIB + o3, 0, S.qkv, 3 * DD, 0, 0, 64 * 3 * DD);
        sattn_k<<<dim3(BB, HH), 64>>>();
        gemm_k<<<dim3(16, 1, 8), 256>>>(S.attn, DD, 0, SAOW + oDD, DD, 0, S.part, DD, 64, DD, 8);
        combine_k<<<256, 256>>>(S.part, 8, 64, DD, SAOB + o1, 0, S.q, DD, 0, 2, 64 * DD);
        // cross-attn (token 0 over frame_tokens, token 1 over kv_salient)
        ln_k<<<64, 256>>>(S.q, LN2G + o1, LN2B + o1, S.x);
        cross_attn(S, FT, NN, 16, CGIW + o3DD, CGIB + o3, CGOW + oDD, CGOB + o1, 0);
        cross_attn(S, KV, KVN, 8, CSIW + o3DD, CSIB + o3, CSOW + oDD, CSOB + o1, 1);
        // FFN
        ln_k<<<64, 256>>>(S.q, LN3G + o1, LN3B + o1, S.x);
        gemm_k<<<dim3(64, 1, 8), 256>>>(S.x, DD, 0, F1W + o4DD, DD, 0, S.part, 4 * DD, 64, DD, 8);
        combine_k<<<1024, 256>>>(S.part, 8, 64, 4 * DD, F1B + o4D, 0, S.h, 4 * DD, 0, 1, 64 * 4 * DD);
        gemm_k<<<dim3(16, 1, 16), 256>>>(S.h, 4 * DD, 0, F2W + o4DD, 4 * DD, 0, S.part, DD, 64, 4 * DD, 16);
        combine_k<<<256, 256>>>(S.part, 16, 64, DD, F2B + o1, 0, S.q, DD, 0, 2, 64 * DD);
    }
    ln_k<<<64, 256>>>(S.q, OUTG, OUTB, (float*)d_out);
}

// round 12
// speedup vs baseline: 1.7832x; 1.7832x over previous
#include <cuda_runtime.h>
#include <math.h>

#define BB 32
#define NN 4096
#define KVN 1024
#define DD 1024
#define HH 16
#define LL 2
#define MAXFV 4096
#define MS 32   // mean slices

// ---------- scratch ----------
__device__ __align__(16) float g_q[64 * DD];
__device__ __align__(16) float g_x[64 * DD];
__device__ __align__(16) float g_qkv[64 * 3 * DD];
__device__ __align__(16) float g_attn[64 * DD];
__device__ __align__(16) float g_qp[BB * DD];
__device__ __align__(16) float g_u[BB * HH * DD];
__device__ __align__(16) float g_c[BB * HH * DD];
__device__ __align__(16) float g_scores[BB * HH * NN];
__device__ __align__(16) float g_part[16 * 64 * 4096];
__device__ __align__(16) float g_cpart[16 * BB * HH * DD];
__device__ __align__(16) float g_mpart[MS * BB * DD];
__device__ __align__(16) float g_h[64 * 4096];

// ---------- packed f32x2 helpers ----------
__device__ __forceinline__ unsigned long long pack2(float lo, float hi) {
    unsigned long long r;
    asm("mov.b64 %0, {%1, %2};" : "=l"(r) : "f"(lo), "f"(hi));
    return r;
}
__device__ __forceinline__ float2 unpack2(unsigned long long v) {
    float2 r;
    asm("mov.b64 {%0, %1}, %2;" : "=f"(r.x), "=f"(r.y) : "l"(v));
    return r;
}
__device__ __forceinline__ void ffma2(unsigned long long& d, unsigned long long a,
                                      unsigned long long b) {
    asm("fma.rn.f32x2 %0, %1, %2, %0;" : "+l"(d) : "l"(a), "l"(b));
}

// ---------- block reductions ----------
__device__ __forceinline__ float blkredSum(float v) {
    __shared__ float sm[8];
    __shared__ float outv;
    int tid = threadIdx.x;
#pragma unroll
    for (int o = 16; o; o >>= 1) v += __shfl_xor_sync(0xffffffffu, v, o);
    if ((tid & 31) == 0) sm[tid >> 5] = v;
    __syncthreads();
    if (tid == 0) {
        float a = 0.f;
        int nw = blockDim.x >> 5;
        for (int w = 0; w < nw; w++) a += sm[w];
        outv = a;
    }
    __syncthreads();
    float r = outv;
    __syncthreads();
    return r;
}

__device__ __forceinline__ float blkredMax(float v) {
    __shared__ float sm[8];
    __shared__ float outv;
    int tid = threadIdx.x;
#pragma unroll
    for (int o = 16; o; o >>= 1) v = fmaxf(v, __shfl_xor_sync(0xffffffffu, v, o));
    if ((tid & 31) == 0) sm[tid >> 5] = v;
    __syncthreads();
    if (tid == 0) {
        float a = -1e30f;
        int nw = blockDim.x >> 5;
        for (int w = 0; w < nw; w++) a = fmaxf(a, sm[w]);
        outv = a;
    }
    __syncthreads();
    float r = outv;
    __syncthreads();
    return r;
}

// ---------- partial mean of frame_tokens: grid (2, BB, MS), block 128 ----------
__global__ void meanpart_k(const float* __restrict__ X) {
    int b = blockIdx.y, s = blockIdx.z;
    int c0 = blockIdx.x * 512 + threadIdx.x * 4;
    const int RS = NN / MS;
    const float* base = X + ((size_t)b * NN + (size_t)s * RS) * DD + c0;
    float4 acc = make_float4(0.f, 0.f, 0.f, 0.f);
    for (int j = 0; j < RS; j += 4) {
        float4 v0 = *(const float4*)(base + (size_t)(j + 0) * DD);
        float4 v1 = *(const float4*)(base + (size_t)(j + 1) * DD);
        float4 v2 = *(const float4*)(base + (size_t)(j + 2) * DD);
        float4 v3 = *(const float4*)(base + (size_t)(j + 3) * DD);
        acc.x += (v0.x + v1.x) + (v2.x + v3.x);
        acc.y += (v0.y + v1.y) + (v2.y + v3.y);
        acc.z += (v0.z + v1.z) + (v2.z + v3.z);
        acc.w += (v0.w + v1.w) + (v2.w + v3.w);
    }
    *(float4*)(g_mpart + (size_t)(s * BB + b) * DD + c0) = acc;
}

// ---------- q init: grid 256, block 256 ----------
__global__ void initq_k(const float* __restrict__ max_init,
                        const float* __restrict__ qbase,
                        const float* __restrict__ rolew,
                        const float* __restrict__ timew,
                        const int* __restrict__ fidx) {
    int idx = blockIdx.x * 256 + threadIdx.x;
    int b = idx >> 11, r = idx & 2047, t = r >> 10, d = r & 1023;
    float base;
    if (t == 0) {
        float m = 0.f;
#pragma unroll
        for (int s = 0; s < MS; s++) m += g_mpart[(size_t)(s * BB + b) * DD + d];
        base = m * (1.0f / NN);
    } else {
        base = max_init[b * DD + d];
    }
    int fi = fidx[b];
    fi = fi < 0 ? 0 : (fi > MAXFV - 1 ? MAXFV - 1 : fi);
    g_q[idx] = base + qbase[t * DD + d] + rolew[t * DD + d] + timew[(size_t)fi * DD + d];
}

// ---------- LayerNorm rows: grid rows, block 256 ----------
__global__ void ln_k(const float* __restrict__ in, const float* __restrict__ gg,
                     const float* __restrict__ bb, float* __restrict__ out) {
    int row = blockIdx.x, tid = threadIdx.x;
    float4 xv = ((const float4*)(in + (size_t)row * DD))[tid];
    float s = blkredSum(xv.x + xv.y + xv.z + xv.w);
    float mean = s * (1.0f / DD);
    float d0 = xv.x - mean, d1 = xv.y - mean, d2 = xv.z - mean, d3 = xv.w - mean;
    float ss = blkredSum(d0 * d0 + d1 * d1 + d2 * d2 + d3 * d3);
    float inv = rsqrtf(ss * (1.0f / DD) + 1e-5f);
    float4 g4 = ((const float4*)gg)[tid];
    float4 b4 = ((const float4*)bb)[tid];
    float4 o;
    o.x = d0 * inv * g4.x + b4.x;
    o.y = d1 * inv * g4.y + b4.y;
    o.z = d2 * inv * g4.z + b4.z;
    o.w = d3 * inv * g4.w + b4.w;
    ((float4*)(out + (size_t)row * DD))[tid] = o;
}

// ---------- split-K GEMM, double-buffered smem + register prefetch + FFMA2 ----------
// part[bt][s][m][n] = sum_{k in slice} A[m,k]*W[n,k]
// grid (Ntot/64, 1, nbatch*SK), block 256
__global__ void gemm_k(const float* __restrict__ A, int lda, long long sA,
                       const float* __restrict__ W, int ldw, long long sW,
                       float* __restrict__ part, int Ntot, int M, int Ktot, int SK) {
    int z = blockIdx.z;
    int bt = z / SK, s = z - bt * SK;
    A += (long long)bt * sA;
    W += (long long)bt * sW;
    float* P = part + ((long long)(bt * SK + s) * M) * Ntot;
    int Ks = Ktot / SK, kbase = s * Ks;
    int n0 = blockIdx.x * 64;
    __shared__ __align__(16) float As[2][16][68];
    __shared__ __align__(16) float Ws[2][16][68];
    int tid = threadIdx.x;
    int tx = tid & 15, ty = tid >> 4;
    int lr = tid >> 2, lc = (tid & 3) * 4;
    unsigned long long acc01[4], acc23[4];
#pragma unroll
    for (int j = 0; j < 4; j++) { acc01[j] = 0ull; acc23[j] = 0ull; }
    const float* Ap = A + (long long)lr * lda + kbase + lc;
    const float* Wp = W + (long long)(n0 + lr) * ldw + kbase + lc;
    int nc = Ks >> 4;
    // prologue: chunk 0 -> buf 0
    float4 av = make_float4(0.f, 0.f, 0.f, 0.f), wv;
    if (lr < M) av = *(const float4*)Ap;
    wv = *(const float4*)Wp;
    As[0][lc + 0][lr] = av.x; As[0][lc + 1][lr] = av.y;
    As[0][lc + 2][lr] = av.z; As[0][lc + 3][lr] = av.w;
    Ws[0][lc + 0][lr] = wv.x; Ws[0][lc + 1][lr] = wv.y;
    Ws[0][lc + 2][lr] = wv.z; Ws[0][lc + 3][lr] = wv.w;
    __syncthreads();
    for (int c = 0; c < nc; c++) {
        int cur = c & 1;
        if (c + 1 < nc) {          // issue next chunk's LDGs before compute
            av = make_float4(0.f, 0.f, 0.f, 0.f);
            if (lr < M) av = *(const float4*)(Ap + (c + 1) * 16);
            wv = *(const float4*)(Wp + (c + 1) * 16);
        }
#pragma unroll
        for (int kk = 0; kk < 16; kk++) {
            float4 a4 = *(const float4*)&As[cur][kk][ty * 4];
            float4 w4 = *(const float4*)&Ws[cur][kk][tx * 4];
            unsigned long long a01 = pack2(a4.x, a4.y);
            unsigned long long a23 = pack2(a4.z, a4.w);
            unsigned long long w0 = pack2(w4.x, w4.x);
            unsigned long long w1 = pack2(w4.y, w4.y);
            unsigned long long w2 = pack2(w4.z, w4.z);
            unsigned long long w3 = pack2(w4.w, w4.w);
            ffma2(acc01[0], a01, w0); ffma2(acc23[0], a23, w0);
            ffma2(acc01[1], a01, w1); ffma2(acc23[1], a23, w1);
            ffma2(acc01[2], a01, w2); ffma2(acc23[2], a23, w2);
            ffma2(acc01[3], a01, w3); ffma2(acc23[3], a23, w3);
        }
        if (c + 1 < nc) {
            int nxt = cur ^ 1;
            As[nxt][lc + 0][lr] = av.x; As[nxt][lc + 1][lr] = av.y;
            As[nxt][lc + 2][lr] = av.z; As[nxt][lc + 3][lr] = av.w;
            Ws[nxt][lc + 0][lr] = wv.x; Ws[nxt][lc + 1][lr] = wv.y;
            Ws[nxt][lc + 2][lr] = wv.z; Ws[nxt][lc + 3][lr] = wv.w;
        }
        __syncthreads();
    }
    float2 r0 = unpack2(acc01[0]), r1 = unpack2(acc01[1]);
    float2 r2 = unpack2(acc01[2]), r3 = unpack2(acc01[3]);
    float2 s0 = unpack2(acc23[0]), s1 = unpack2(acc23[1]);
    float2 s2 = unpack2(acc23[2]), s3 = unpack2(acc23[3]);
    int m0 = ty * 4, nn = n0 + tx * 4;
    if (m0 + 0 < M) *(float4*)&P[(long long)(m0 + 0) * Ntot + nn] = make_float4(r0.x, r1.x, r2.x, r3.x);
    if (m0 + 1 < M) *(float4*)&P[(long long)(m0 + 1) * Ntot + nn] = make_float4(r0.y, r1.y, r2.y, r3.y);
    if (m0 + 2 < M) *(float4*)&P[(long long)(m0 + 2) * Ntot + nn] = make_float4(s0.x, s1.x, s2.x, s3.x);
    if (m0 + 3 < M) *(float4*)&P[(long long)(m0 + 3) * Ntot + nn] = make_float4(s0.y, s1.y, s2.y, s3.y);
}

// ---------- combine split-K + bias; mode 0 store, 1 gelu-store, 2 residual-add ----------
__global__ void combine_k(const float* __restrict__ part, int S, int M, int N,
                          const float* __restrict__ bias, int biasBatch,
                          float* __restrict__ dst, int dstRow, int dstBatch,
                          int mode, int total) {
    int idx = blockIdx.x * 256 + threadIdx.x;
    if (idx >= total) return;
    int bt = idx / (M * N);
    int r = idx - bt * M * N;
    int m = r / N, n = r - m * N;
    float v = 0.f;
    const float* p = part + ((long long)bt * S * M + m) * N + n;
    for (int s = 0; s < S; s++) v += p[(long long)s * M * N];
    if (bias) v += bias[bt * biasBatch + n];
    if (mode == 1) v = 0.5f * v * (1.0f + erff(v * 0.70710678118654752f));
    float* dp = dst + (long long)bt * dstBatch + (long long)m * dstRow + n;
    if (mode == 2) *dp += v; else *dp = v;
}

// ---------- self-attn over 2 tokens: grid (BB, HH), block 64 ----------
__global__ void sattn_k() {
    int b = blockIdx.x, h = blockIdx.y, i = threadIdx.x;
    int r0 = (b * 2) * 3 * DD, r1 = r0 + 3 * DD;
    int cq = h * 64 + i, ck = DD + cq, cv = 2 * DD + cq;
    float q0 = g_qkv[r0 + cq], q1 = g_qkv[r1 + cq];
    float k0 = g_qkv[r0 + ck], k1 = g_qkv[r1 + ck];
    float v0 = g_qkv[r0 + cv], v1 = g_qkv[r1 + cv];
    __shared__ float red[4][64];
    red[0][i] = q0 * k0; red[1][i] = q0 * k1;
    red[2][i] = q1 * k0; red[3][i] = q1 * k1;
    __syncthreads();
    __shared__ float ss[4];
    if (i < 4) {
        float a = 0.f;
        for (int j = 0; j < 64; j++) a += red[i][j];
        ss[i] = a * 0.125f;
    }
    __syncthreads();
    float m0 = fmaxf(ss[0], ss[1]);
    float e00 = __expf(ss[0] - m0), e01 = __expf(ss[1] - m0);
    float o0 = (e00 * v0 + e01 * v1) / (e00 + e01);
    float m1 = fmaxf(ss[2], ss[3]);
    float e10 = __expf(ss[2] - m1), e11 = __expf(ss[3] - m1);
    float o1 = (e10 * v0 + e11 * v1) / (e10 + e11);
    g_attn[(size_t)(b * 2) * DD + h * 64 + i] = o0;
    g_attn[(size_t)(b * 2 + 1) * DD + h * 64 + i] = o1;
}

// ---------- u = 0.125 * Wk_h^T (qp_h + bq_h): grid (HH, DD/64), block 256 ----------
__global__ void u_k(const float* __restrict__ Wk, const float* __restrict__ bq) {
    int h = blockIdx.x;
    int d0 = blockIdx.y * 64;
    int tid = threadIdx.x;
    __shared__ float qps[32 * 64];
    for (int t = tid; t < 2048; t += 256) {
        int b = t >> 6, i = t & 63;
        qps[t] = g_qp[b * DD + h * 64 + i] + bq[h * 64 + i];
    }
    __syncthreads();
    int d = d0 + (tid & 63);
    int bg = tid >> 6;
    float acc[8];
#pragma unroll
    for (int r = 0; r < 8; r++) acc[r] = 0.f;
    const float* wp = Wk + (size_t)(h * 64) * DD + d;
    for (int i = 0; i < 64; i++) {
        float w = wp[(size_t)i * DD];
#pragma unroll
        for (int r = 0; r < 8; r++) acc[r] += qps[(bg * 8 + r) * 64 + i] * w;
    }
#pragma unroll
    for (int r = 0; r < 8; r++)
        g_u[((size_t)(bg * 8 + r) * HH + h) * DD + d] = acc[r] * 0.125f;
}

// ---------- scores S[b,h,j] = u[b,h,:].x[b,j,:] — double-buffered + FFMA2 ----------
// grid (Nkv/128, BB), block 128
__global__ void score_k(const float* __restrict__ X, int Nkv) {
    int b = blockIdx.y;
    int jb = blockIdx.x * 128;
    int tid = threadIdx.x;
    int tx = tid & 3, ty = tid >> 2;  // tx: h-group, ty: j-group
    __shared__ __align__(16) float Xs[2][32][132];   // [buf][kk][j]
    __shared__ __align__(16) float Us[2][32][20];    // [buf][kk][h]
    unsigned long long acc01[4], acc23[4];
#pragma unroll
    for (int j = 0; j < 4; j++) { acc01[j] = 0ull; acc23[j] = 0ull; }
    const float* Xb = X + ((size_t)b * Nkv + jb) * DD;
    const float* Ub = g_u + (size_t)b * HH * DD;
    int lr8 = tid >> 3, lc = (tid & 7) * 4;
    const float* Xp = Xb + (size_t)lr8 * DD + lc;   // rows lr8 + 16*q
    const float* Up = Ub + (size_t)lr8 * DD + lc;
    float4 xv[8], uv;
    // prologue: chunk 0 -> buf 0
#pragma unroll
    for (int q = 0; q < 8; q++) xv[q] = *(const float4*)(Xp + (size_t)(q * 16) * DD);
    uv = *(const float4*)Up;
#pragma unroll
    for (int q = 0; q < 8; q++) {
        int row = lr8 + q * 16;
        Xs[0][lc + 0][row] = xv[q].x; Xs[0][lc + 1][row] = xv[q].y;
        Xs[0][lc + 2][row] = xv[q].z; Xs[0][lc + 3][row] = xv[q].w;
    }
    Us[0][lc + 0][lr8] = uv.x; Us[0][lc + 1][lr8] = uv.y;
    Us[0][lc + 2][lr8] = uv.z; Us[0][lc + 3][lr8] = uv.w;
    __syncthreads();
    const int NC = DD / 32;  // 32 chunks
    for (int c = 0; c < NC; c++) {
        int cur = c & 1;
        if (c + 1 < NC) {   // prefetch next chunk while computing
            int k0 = (c + 1) * 32;
#pragma unroll
            for (int q = 0; q < 8; q++) xv[q] = *(const float4*)(Xp + (size_t)(q * 16) * DD + k0);
            uv = *(const float4*)(Up + k0);
        }
#pragma unroll
        for (int kk = 0; kk < 32; kk++) {
            float4 a4 = *(const float4*)&Xs[cur][kk][ty * 4];
            float4 w4 = *(const float4*)&Us[cur][kk][tx * 4];
            unsigned long long a01 = pack2(a4.x, a4.y);
            unsigned long long a23 = pack2(a4.z, a4.w);
            unsigned long long w0 = pack2(w4.x, w4.x);
            unsigned long long w1 = pack2(w4.y, w4.y);
            unsigned long long w2 = pack2(w4.z, w4.z);
            unsigned long long w3 = pack2(w4.w, w4.w);
            ffma2(acc01[0], a01, w0); ffma2(acc23[0], a23, w0);
            ffma2(acc01[1], a01, w1); ffma2(acc23[1], a23, w1);
            ffma2(acc01[2], a01, w2); ffma2(acc23[2], a23, w2);
            ffma2(acc01[3], a01, w3); ffma2(acc23[3], a23, w3);
        }
        if (c + 1 < NC) {
            int nxt = cur ^ 1;
#pragma unroll
            for (int q = 0; q < 8; q++) {
                int row = lr8 + q * 16;
                Xs[nxt][lc + 0][row] = xv[q].x; Xs[nxt][lc + 1][row] = xv[q].y;
                Xs[nxt][lc + 2][row] = xv[q].z; Xs[nxt][lc + 3][row] = xv[q].w;
            }
            Us[nxt][lc + 0][lr8] = uv.x; Us[nxt][lc + 1][lr8] = uv.y;
            Us[nxt][lc + 2][lr8] = uv.z; Us[nxt][lc + 3][lr8] = uv.w;
        }
        __syncthreads();
    }
#pragma unroll
    for (int j = 0; j < 4; j++) {
        float2 p01 = unpack2(acc01[j]);
        float2 p23 = unpack2(acc23[j]);
        float* Sp = g_scores + ((size_t)b * HH + tx * 4 + j) * Nkv + jb + ty * 4;
        *(float4*)Sp = make_float4(p01.x, p01.y, p23.x, p23.y);
    }
}

// ---------- softmax in place: grid BB*HH, block 256 ----------
__global__ void softmax_k(int Nkv) {
    int tid = threadIdx.x;
    float* S = g_scores + (size_t)blockIdx.x * Nkv;
    int cnt = Nkv >> 8;
    float v[16];
    float mx = -1e30f;
    for (int c = 0; c < cnt; c++) { v[c] = S[c * 256 + tid]; mx = fmaxf(mx, v[c]); }
    mx = blkredMax(mx);
    float sum = 0.f;
    for (int c = 0; c < cnt; c++) { v[c] = __expf(v[c] - mx); sum += v[c]; }
    sum = blkredSum(sum);
    float inv = 1.0f / sum;
    for (int c = 0; c < cnt; c++) S[c * 256 + tid] = v[c] * inv;
}

// ---------- accumulate c_part[s][b,h,:] = sum_j p*x — FFMA2: grid (2, BB, 16), block 128 ----------
__global__ void accum_k(const float* __restrict__ X, int Nkv) {
    int b = blockIdx.y, s = blockIdx.z, tid = threadIdx.x;
    int d0 = blockIdx.x * 512 + tid * 4;
    int Nt = Nkv >> 4;
    int jbase = s * Nt;
    __shared__ unsigned long long ps[16][64];
    unsigned long long acc01[16], acc23[16];
#pragma unroll
    for (int h = 0; h < 16; h++) { acc01[h] = 0ull; acc23[h] = 0ull; }
    for (int jc = 0; jc < Nt; jc += 64) {
        for (int t = tid; t < 1024; t += 128) {
            int h = t >> 6, jj = t & 63;
            float p = g_scores[((size_t)b * HH + h) * Nkv + jbase + jc + jj];
            ps[h][jj] = pack2(p, p);
        }
        __syncthreads();
        const float* Xb = X + ((size_t)b * Nkv + jbase + jc) * DD + d0;
#pragma unroll 2
        for (int jj = 0; jj < 64; jj++) {
            float4 x4 = *(const float4*)(Xb + (size_t)jj * DD);
            unsigned long long x01 = pack2(x4.x, x4.y);
            unsigned long long x23 = pack2(x4.z, x4.w);
#pragma unroll
            for (int h = 0; h < 16; h++) {
                unsigned long long pd = ps[h][jj];
                ffma2(acc01[h], x01, pd);
                ffma2(acc23[h], x23, pd);
            }
        }
        __syncthreads();
    }
#pragma unroll
    for (int h = 0; h < 16; h++) {
        float2 a = unpack2(acc01[h]);
        float2 c = unpack2(acc23[h]);
        *(float4*)(g_cpart + ((size_t)(s * BB + b) * HH + h) * DD + d0) =
            make_float4(a.x, a.y, c.x, c.y);
    }
}

// ---------- host side ----------
struct Scratch {
    float *q, *x, *qkv, *attn, *qp, *c, *part, *cpart, *h;
};

static void cross_attn(const Scratch& S, const float* X, int Nkv,
                       const float* inW, const float* inB,
                       const float* outW, const float* outB, int tok) {
    gemm_k<<<dim3(16, 1, 8), 256>>>(S.x + tok * DD, 2 * DD, 0, inW, DD, 0, S.part, DD, BB, DD, 8);
    combine_k<<<128, 256>>>(S.part, 8, BB, DD, nullptr, 0, S.qp, DD, 0, 0, BB * DD);
    u_k<<<dim3(HH, DD / 64), 256>>>(inW + (size_t)DD * DD, inB);
    score_k<<<dim3(Nkv / 128, BB), 128>>>(X, Nkv);
    softmax_k<<<BB * HH, 256>>>(Nkv);
    accum_k<<<dim3(2, BB, 16), 128>>>(X, Nkv);
    combine_k<<<2048, 256>>>(S.cpart, 16, BB * HH, DD, nullptr, 0, S.c, DD, 0, 0, BB * HH * DD);
    gemm_k<<<dim3(1, 1, HH * 8), 256>>>(S.c, HH * DD, DD, inW + (size_t)2 * DD * DD, DD,
                                        (long long)64 * DD, S.part, 64, BB, DD, 8);
    combine_k<<<128, 256>>>(S.part, 8, BB, 64, inB + 2 * DD, 64, S.qp, DD, 64, 0, HH * BB * 64);
    gemm_k<<<dim3(16, 1, 8), 256>>>(S.qp, DD, 0, outW, DD, 0, S.part, DD, BB, DD, 8);
    combine_k<<<128, 256>>>(S.part, 8, BB, DD, outB, 0, S.q + tok * DD, 2 * DD, 0, 2, BB * DD);
}

extern "C" void kernel_launch(void* const* d_in, const int* in_sizes, int n_in,
                              void* d_out, int out_size) {
    const float* FT   = (const float*)d_in[0];
    const float* KV   = (const float*)d_in[1];
    const float* MAXI = (const float*)d_in[2];
    const float* QB   = (const float*)d_in[3];
    const float* RW   = (const float*)d_in[4];
    const float* TW   = (const float*)d_in[5];
    const float* LN1G = (const float*)d_in[6];
    const float* LN1B = (const float*)d_in[7];
    const float* SAIW = (const float*)d_in[8];
    const float* SAIB = (const float*)d_in[9];
    const float* SAOW = (const float*)d_in[10];
    const float* SAOB = (const float*)d_in[11];
    const float* LN2G = (const float*)d_in[12];
    const float* LN2B = (const float*)d_in[13];
    const float* CGIW = (const float*)d_in[14];
    const float* CGIB = (const float*)d_in[15];
    const float* CGOW = (const float*)d_in[16];
    const float* CGOB = (const float*)d_in[17];
    const float* CSIW = (const float*)d_in[18];
    const float* CSIB = (const float*)d_in[19];
    const float* CSOW = (const float*)d_in[20];
    const float* CSOB = (const float*)d_in[21];
    const float* LN3G = (const float*)d_in[22];
    const float* LN3B = (const float*)d_in[23];
    const float* F1W  = (const float*)d_in[24];
    const float* F1B  = (const float*)d_in[25];
    const float* F2W  = (const float*)d_in[26];
    const float* F2B  = (const float*)d_in[27];
    const float* OUTG = (const float*)d_in[28];
    const float* OUTB = (const float*)d_in[29];
    const int*   FIDX = (const int*)d_in[30];

    Scratch S;
    cudaGetSymbolAddress((void**)&S.q,     g_q);
    cudaGetSymbolAddress((void**)&S.x,     g_x);
    cudaGetSymbolAddress((void**)&S.qkv,   g_qkv);
    cudaGetSymbolAddress((void**)&S.attn,  g_attn);
    cudaGetSymbolAddress((void**)&S.qp,    g_qp);
    cudaGetSymbolAddress((void**)&S.c,     g_c);
    cudaGetSymbolAddress((void**)&S.part,  g_part);
    cudaGetSymbolAddress((void**)&S.cpart, g_cpart);
    cudaGetSymbolAddress((void**)&S.h,     g_h);

    meanpart_k<<<dim3(2, BB, MS), 128>>>(FT);
    initq_k<<<256, 256>>>(MAXI, QB, RW, TW, FIDX);

    for (int l = 0; l < LL; l++) {
        size_t o1 = (size_t)l * DD, o3 = (size_t)l * 3 * DD;
        size_t oDD = (size_t)l * DD * DD, o3DD = (size_t)l * 3 * DD * DD;
        size_t o4DD = (size_t)l * 4 * DD * DD, o4D = (size_t)l * 4 * DD;
        // self-attn
        ln_k<<<64, 256>>>(S.q, LN1G + o1, LN1B + o1, S.x);
        gemm_k<<<dim3(48, 1, 8), 256>>>(S.x, DD, 0, SAIW + o3DD, DD, 0, S.part, 3 * DD, 64, DD, 8);
        combine_k<<<768, 256>>>(S.part, 8, 64, 3 * DD, SAIB + o3, 0, S.qkv, 3 * DD, 0, 0, 64 * 3 * DD);
        sattn_k<<<dim3(BB, HH), 64>>>();
        gemm_k<<<dim3(16, 1, 8), 256>>>(S.attn, DD, 0, SAOW + oDD, DD, 0, S.part, DD, 64, DD, 8);
        combine_k<<<256, 256>>>(S.part, 8, 64, DD, SAOB + o1, 0, S.q, DD, 0, 2, 64 * DD);
        // cross-attn
        ln_k<<<64, 256>>>(S.q, LN2G + o1, LN2B + o1, S.x);
        cross_attn(S, FT, NN, CGIW + o3DD, CGIB + o3, CGOW + oDD, CGOB + o1, 0);
        cross_attn(S, KV, KVN, CSIW + o3DD, CSIB + o3, CSOW + oDD, CSOB + o1, 1);
        // FFN
        ln_k<<<64, 256>>>(S.q, LN3G + o1, LN3B + o1, S.x);
        gemm_k<<<dim3(64, 1, 8), 256>>>(S.x, DD, 0, F1W + o4DD, DD, 0, S.part, 4 * DD, 64, DD, 8);
        combine_k<<<1024, 256>>>(S.part, 8, 64, 4 * DD, F1B + o4D, 0, S.h, 4 * DD, 0, 1, 64 * 4 * DD);
        gemm_k<<<dim3(16, 1, 16), 256>>>(S.h, 4 * DD, 0, F2W + o4DD, 4 * DD, 0, S.part, DD, 64, 4 * DD, 16);
        combine_k<<<256, 256>>>(S.part, 16, 64, DD, F2B + o1, 0, S.q, DD, 0, 2, 64 * DD);
    }
    ln_k<<<64, 256>>>(S.q, OUTG, OUTB, (float*)d_out);
}